// round 17
// baseline (speedup 1.0000x reference)
#include <cuda_runtime.h>
#include <cuda_fp16.h>
#include <cstdint>

// ---------------- problem constants ----------------
#define NMAX   200000
#define CCH    64
#define KTAPS  9
#define TN     128          // rows per block (MMA M)
#define NTHR   128
#define LEAK   0.01f
#define EPS_BN 1e-5f
#define WSCALE 256.0f
#define INV_WSCALE (1.0f / 256.0f)

// dynamic smem: 2 stages x 32K (2 taps per stage) / epilogue tile
#define TAP_BYTES   16384
#define STAGE_BYTES 32768
#define DSM_BYTES   65536
#define SC_STRIDE 68        // fp32 epilogue tile stride (floats)
#define SH_STRIDE 72        // fp16 epilogue tile stride (halves)

// B fragment layout (single plane): per tap = 16 chunks * 32 lanes * 8 halves
#define FRAG_TAP_HALVES   4096
#define FRAG_TENSOR_HALVES (KTAPS * FRAG_TAP_HALVES)   // 36864

// ---------------- scratch (no cudaMalloc allowed) ----------------
__device__ __half g_fS [((size_t)NMAX + 1) * 64];
__device__ __half g_aSa[((size_t)NMAX + 1) * 64];   // shortcut branch
__device__ __half g_aSb[((size_t)NMAX + 1) * 64];   // main branch
__device__ __half g_y2h[(size_t)NMAX * 64];         // y2 (shortcut output) fp16
__device__ __half g_wFrag[4 * FRAG_TENSOR_HALVES];
__device__ __half g_biasHi[4 * 64 * 16];            // [tensor][o*16 + tap], x256
__device__ float g_sums [4][CCH];
__device__ float g_sumsq[4][CCH];

// ---------------- helpers ----------------
__device__ __forceinline__ uint32_t smem_u32(const void* p) {
    uint32_t a;
    asm("{ .reg .u64 t; cvta.to.shared.u64 t, %1; cvt.u32.u64 %0, t; }" : "=r"(a) : "l"(p));
    return a;
}
__device__ __forceinline__ void ldsm4(uint32_t* r, uint32_t addr) {
    asm volatile("ldmatrix.sync.aligned.m8n8.x4.shared.b16 {%0,%1,%2,%3}, [%4];"
        : "=r"(r[0]), "=r"(r[1]), "=r"(r[2]), "=r"(r[3]) : "r"(addr));
}
__device__ __forceinline__ void mma16816(float* c, const uint32_t* a, const uint32_t* b) {
    asm volatile("mma.sync.aligned.m16n8k16.row.col.f32.f16.f16.f32 "
        "{%0,%1,%2,%3}, {%4,%5,%6,%7}, {%8,%9}, {%0,%1,%2,%3};"
        : "+f"(c[0]), "+f"(c[1]), "+f"(c[2]), "+f"(c[3])
        : "r"(a[0]), "r"(a[1]), "r"(a[2]), "r"(a[3]), "r"(b[0]), "r"(b[1]));
}
__device__ __forceinline__ uint32_t pack2h(float a, float b) {
    __half2 h = __floats2half2_rn(a, b);
    return *(uint32_t*)&h;
}

// one packed fp16x2 B-frag reg: {W[kk][nn], W[kk+1][nn]} * scale * WSCALE
__device__ __forceinline__ uint32_t frag_reg1(const float* __restrict__ src,
                                              const float* __restrict__ sck,
                                              int kk, int nn) {
    const float s0 = sck ? sck[kk] : 1.f;
    const float s1 = sck ? sck[kk + 1] : 1.f;
    return pack2h(src[kk * 64 + nn] * s0 * WSCALE,
                  src[(kk + 1) * 64 + nn] * s1 * WSCALE);
}

// fragment slots per tap: 512 uint4 = [chunk = q*4 + wn*2 + p][lane]
__device__ __forceinline__ void write_frags(const float* __restrict__ src,
                                            const float* __restrict__ sck,
                                            __half* __restrict__ dstTap, int tid) {
#pragma unroll
    for (int i = 0; i < 2; ++i) {
        const int idx = tid + i * 256;
        const int lane = idx & 31;
        const int chunk = idx >> 5;
        const int q = chunk >> 2, wn = (chunk >> 1) & 1, p = chunk & 1;
        const int m = lane & 3, nr = lane >> 2;
        const int k0 = 16 * q;
        const int n0 = wn * 32 + 16 * p + nr;
        uint4 o;
        o.x = frag_reg1(src, sck, k0 + 2 * m,     n0);
        o.y = frag_reg1(src, sck, k0 + 2 * m,     n0 + 8);
        o.z = frag_reg1(src, sck, k0 + 8 + 2 * m, n0);
        o.w = frag_reg1(src, sck, k0 + 8 + 2 * m, n0 + 8);
        ((uint4*)dstTap)[idx] = o;
    }
}

// ---------------- merged preamble: split + weight frags + zero ----------------
__global__ __launch_bounds__(256)
void pre_k(const float* __restrict__ features,
           const float* __restrict__ w1, const float* __restrict__ w2,
           int nTotal, int gridS)
{
    const int bid = blockIdx.x, tid = threadIdx.x;
    if (bid < gridS) {
        const int row = bid * 256 + tid;
        if (row >= nTotal) return;
        const float4* s = (const float4*)(features + (size_t)row * CCH);
        uint4* d = (uint4*)(g_fS + (size_t)row * 64);
#pragma unroll
        for (int g = 0; g < 8; ++g) {
            const float4 v0 = s[2 * g], v1 = s[2 * g + 1];
            uint4 o;
            o.x = pack2h(v0.x, v0.y);
            o.y = pack2h(v0.z, v0.w);
            o.z = pack2h(v1.x, v1.y);
            o.w = pack2h(v1.z, v1.w);
            d[g] = o;
        }
        return;
    }
    const int j = bid - gridS;
    if (j < 2 * KTAPS) {
        const int t = (j < KTAPS) ? 0 : 2;
        const int k = j % KTAPS;
        const float* src = ((t == 0) ? w1 : w2) + k * 4096;
        __half* dst = g_wFrag + (size_t)t * FRAG_TENSOR_HALVES + (size_t)k * FRAG_TAP_HALVES;
        write_frags(src, nullptr, dst, tid);
        return;
    }
    ((float*)g_sums)[tid]  = 0.f;
    ((float*)g_sumsq)[tid] = 0.f;
#pragma unroll
    for (int r = 0; r < 8; ++r)
        ((uint32_t*)g_biasHi)[tid + r * 256] = 0u;
    if (tid < 32) ((uint32_t*)(g_fS + (size_t)nTotal * 64))[tid] = 0u;
    else if (tid < 64) ((uint32_t*)(g_aSa + (size_t)nTotal * 64))[tid - 32] = 0u;
    else if (tid < 96) ((uint32_t*)(g_aSb + (size_t)nTotal * 64))[tid - 64] = 0u;
}

// fold BN(stage) into weights -> fragment layout; bias_k[o] = 256*sum_c shift[c]*W[c,o]
__global__ void prep_fold2_k(const float* __restrict__ wA, const float* __restrict__ wB,
                             const float* __restrict__ gA, const float* __restrict__ bA,
                             const float* __restrict__ gB, const float* __restrict__ bB,
                             float invN) {
    __shared__ float sc[64], sh[64];
    const int sel = blockIdx.x / KTAPS;
    const int k = blockIdx.x % KTAPS, tid = threadIdx.x;
    const float* w = sel ? wB : wA;
    const float* gamma = sel ? gB : gA;
    const float* beta  = sel ? bB : bA;
    const int stage = sel ? 2 : 0;
    const int tensor = sel ? 3 : 1;
    if (tid < 64) {
        const float m = g_sums[stage][tid] * invN;
        const float v = g_sumsq[stage][tid] * invN - m * m;
        const float a = gamma[tid] * rsqrtf(v + EPS_BN);
        sc[tid] = a;
        sh[tid] = beta[tid] - m * a;
    }
    __syncthreads();
    const float* src = w + (size_t)k * 4096;
    __half* dst = g_wFrag + (size_t)tensor * FRAG_TENSOR_HALVES + (size_t)k * FRAG_TAP_HALVES;
    write_frags(src, sc, dst, tid);
    if (tid < 64) {
        float s = 0.f;
#pragma unroll 8
        for (int c = 0; c < 64; ++c) s += sh[c] * src[c * 64 + tid];
        g_biasHi[tensor * 1024 + tid * 16 + k] = __float2half_rn(s * WSCALE);
    }
}

// ---------------- main conv kernel ----------------
// outMode: 0 = fp32 rows (dstF), nonzero = fp16 rows (dstH)
template <bool HAS_BIAS>
__global__ __launch_bounds__(NTHR, 3)
void conv_mma_k(const __half* __restrict__ src0, const __half* __restrict__ src1,
                const int* __restrict__ nbr0, const int* __restrict__ nbr1,
                int wt0, int wt1,
                float* __restrict__ dstF0, float* __restrict__ dstF1,
                __half* __restrict__ dstH0, __half* __restrict__ dstH1,
                int om0, int om1,
                int nTotal, int stage0, int stage1)
{
    extern __shared__ __align__(128) char smemc[];
    __shared__ uint4 sBBh[128];       // bias [64 o][16 taps] fp16
    __shared__ int   sNbr[128 * KTAPS];

    const int sel = blockIdx.y;
    const __half* __restrict__ src = sel ? src1 : src0;
    const int*    __restrict__ nbr = sel ? nbr1 : nbr0;
    const int wtIdx = sel ? wt1 : wt0;
    float*  __restrict__ dstF = sel ? dstF1 : dstF0;
    __half* __restrict__ dstH = sel ? dstH1 : dstH0;
    const int outMode = sel ? om1 : om0;
    const int stage = sel ? stage1 : stage0;

    const int tid   = threadIdx.x;
    const int lane  = tid & 31;
    const int wid   = tid >> 5;
    const int nBase = blockIdx.x * TN;
    const bool rowOK = (nBase + tid) < nTotal;

    const uint32_t sbase = smem_u32(smemc);
    const int wm = wid & 1, wn = wid >> 1;
    const int rowBase = wm * 64;
    const int colBase = wn * 32;
    const int lsw = lane & 7, l15 = lane & 15, l16 = lane >> 4;

#pragma unroll
    for (int j = 0; j < KTAPS; ++j)
        sNbr[tid * KTAPS + j] = rowOK ? nbr[(size_t)(nBase + tid) * KTAPS + j] : nTotal;

    if (HAS_BIAS)
        sBBh[tid] = ((const uint4*)(g_biasHi + wtIdx * 1024))[tid];

    float C[4][4][4];
#pragma unroll
    for (int mt = 0; mt < 4; ++mt)
#pragma unroll
        for (int nt = 0; nt < 4; ++nt)
#pragma unroll
            for (int i = 0; i < 4; ++i) C[mt][nt][i] = 0.f;

    const uint4* bF = (const uint4*)(g_wFrag + (size_t)wtIdx * FRAG_TENSOR_HALVES) + lane;

    const int gRow0  = (wid << 5) + (lane >> 3);
    const int gChunk = lane & 7;
    uint4 pa[8];

    auto tapAddr = [&](int k) -> uint32_t {
        return sbase + (uint32_t)(((k >> 1) & 1) * STAGE_BYTES + (k & 1) * TAP_BYTES);
    };

    auto ldgA = [&](int k) {
#pragma unroll
        for (int it = 0; it < 8; ++it) {
            const int rl = gRow0 + (it << 2);
            const int nidx = sNbr[rl * KTAPS + k];
            pa[it] = *(const uint4*)(src + (size_t)nidx * 64 + (gChunk << 3));
        }
    };
    auto stsA = [&](int k) {
        char* ab = smemc + (tapAddr(k) - sbase);
#pragma unroll
        for (int it = 0; it < 8; ++it) {
            const int rl = gRow0 + (it << 2);
            *(uint4*)(ab + rl * 128 + ((gChunk ^ (rl & 7)) << 4)) = pa[it];
        }
    };
    auto mmaTap = [&](int k) {
        const uint32_t ab = tapAddr(k);
#pragma unroll
        for (int q = 0; q < 4; ++q) {
            const int kg = 2 * q + l16;
            uint32_t a_[4][4];
#pragma unroll
            for (int mt = 0; mt < 4; ++mt) {
                const uint32_t off =
                    (uint32_t)((rowBase + mt * 16 + l15) * 128 + ((kg ^ lsw) << 4));
                ldsm4(a_[mt], ab + off);
            }
            const uint4* bq = bF + (size_t)((k * 4 + q) * 4 + wn * 2) * 32;
            const uint4 f0 = bq[0], f1 = bq[32];
            uint32_t bh[4][2];
            bh[0][0] = f0.x; bh[1][0] = f0.y; bh[0][1] = f0.z; bh[1][1] = f0.w;
            bh[2][0] = f1.x; bh[3][0] = f1.y; bh[2][1] = f1.z; bh[3][1] = f1.w;
#pragma unroll
            for (int mt = 0; mt < 4; ++mt)
#pragma unroll
                for (int nt = 0; nt < 4; ++nt)
                    mma16816(C[mt][nt], a_[mt], bh[nt]);
        }
    };

    __syncthreads();
    ldgA(0); stsA(0);
    ldgA(1); stsA(1);

#pragma unroll
    for (int it = 0; it < 5; ++it) {
        __syncthreads();
        const int k0 = 2 * it, k1 = 2 * it + 1;

        if (k0 + 2 < KTAPS) ldgA(k0 + 2);
        mmaTap(k0);
        if (k0 + 2 < KTAPS) stsA(k0 + 2);

        if (k1 < KTAPS) {
            if (k1 + 2 < KTAPS) ldgA(k1 + 2);
            mmaTap(k1);
            if (k1 + 2 < KTAPS) stsA(k1 + 2);
        }
    }

    // ---- bias MMA ----
    if (HAS_BIAS) {
        uint32_t av[4][4];
        const int fr = lane >> 2, fc = (lane & 3) * 2;
#pragma unroll
        for (int mt = 0; mt < 4; ++mt) {
            const int r0 = rowBase + mt * 16 + fr;
            const int r1 = r0 + 8;
#pragma unroll
            for (int j = 0; j < 4; ++j) {
                const int rr = (j & 1) ? r1 : r0;
                const int c0 = fc + ((j >> 1) << 3);
                uint32_t lo = 0u, hi = 0u;
                if (c0     < KTAPS && sNbr[rr * KTAPS + c0]     < nTotal) lo = 0x3C00u;
                if (c0 + 1 < KTAPS && sNbr[rr * KTAPS + c0 + 1] < nTotal) hi = 0x3C00u;
                av[mt][j] = lo | (hi << 16);
            }
        }
        const uint32_t bhb = smem_u32(sBBh);
        uint32_t bbh[4][2];
#pragma unroll
        for (int p = 0; p < 2; ++p) {
            const uint32_t off = (uint32_t)((colBase + 16 * p + l15) * 32 + l16 * 16);
            uint32_t r[4];
            ldsm4(r, bhb + off);
            bbh[2*p][0] = r[0]; bbh[2*p+1][0] = r[1];
            bbh[2*p][1] = r[2]; bbh[2*p+1][1] = r[3];
        }
#pragma unroll
        for (int mt = 0; mt < 4; ++mt)
#pragma unroll
            for (int nt = 0; nt < 4; ++nt)
                mma16816(C[mt][nt], av[mt], bbh[nt]);
    }

    // ---- epilogue: descale + leaky; stats from registers; store via smem tile ----
    // 1) descale + leaky in-place
#pragma unroll
    for (int mt = 0; mt < 4; ++mt)
#pragma unroll
        for (int nt = 0; nt < 4; ++nt) {
            float* c = C[mt][nt];
#pragma unroll
            for (int i = 0; i < 4; ++i) {
                const float v = c[i] * INV_WSCALE;
                c[i] = (v > 0.f) ? v : LEAK * v;
            }
        }

    // 2) stats from registers: per (nt, col-pair j) sums over this thread's 16 rows
    {
        float sa[4][2], sq[4][2];
#pragma unroll
        for (int nt = 0; nt < 4; ++nt) {
            sa[nt][0] = sa[nt][1] = sq[nt][0] = sq[nt][1] = 0.f;
#pragma unroll
            for (int mt = 0; mt < 4; ++mt) {
                const float* c = C[mt][nt];
                sa[nt][0] += c[0] + c[2];
                sa[nt][1] += c[1] + c[3];
                sq[nt][0] += c[0] * c[0] + c[2] * c[2];
                sq[nt][1] += c[1] * c[1] + c[3] * c[3];
            }
        }
        // reduce over the 8 lanes sharing (lane & 3)
#pragma unroll
        for (int nt = 0; nt < 4; ++nt)
#pragma unroll
            for (int j = 0; j < 2; ++j) {
#pragma unroll
                for (int m = 4; m <= 16; m <<= 1) {
                    sa[nt][j] += __shfl_xor_sync(0xffffffffu, sa[nt][j], m);
                    sq[nt][j] += __shfl_xor_sync(0xffffffffu, sq[nt][j], m);
                }
            }
        if (lane < 4) {
#pragma unroll
            for (int nt = 0; nt < 4; ++nt) {
                const int col = colBase + nt * 8 + lane * 2;
                atomicAdd(&g_sums [stage][col    ], sa[nt][0]);
                atomicAdd(&g_sums [stage][col + 1], sa[nt][1]);
                atomicAdd(&g_sumsq[stage][col    ], sq[nt][0]);
                atomicAdd(&g_sumsq[stage][col + 1], sq[nt][1]);
            }
        }
    }

    // 3) store via smem tile (fp16 tile for fp16 outputs, fp32 tile otherwise)
    __syncthreads();   // taps fully consumed; smem reusable
    const int fg = lane >> 2, ft2 = (lane & 3) * 2;
    if (outMode != 0) {
        __half* sH = (__half*)smemc;                 // [128][SH_STRIDE]
#pragma unroll
        for (int mt = 0; mt < 4; ++mt)
#pragma unroll
            for (int nt = 0; nt < 4; ++nt) {
                const float* c = C[mt][nt];
                const int r0 = rowBase + mt * 16 + fg;
                const int col = colBase + nt * 8 + ft2;
                *(uint32_t*)&sH[r0 * SH_STRIDE + col]       = pack2h(c[0], c[1]);
                *(uint32_t*)&sH[(r0 + 8) * SH_STRIDE + col] = pack2h(c[2], c[3]);
            }
        __syncthreads();
        if (rowOK) {
            const uint4* rowp = (const uint4*)(sH + tid * SH_STRIDE);
            uint4* d = (uint4*)(dstH + (size_t)(nBase + tid) * 64);
#pragma unroll
            for (int g = 0; g < 8; ++g) d[g] = rowp[g];
        }
    } else {
        float* sC = (float*)smemc;                   // [128][SC_STRIDE]
#pragma unroll
        for (int mt = 0; mt < 4; ++mt)
#pragma unroll
            for (int nt = 0; nt < 4; ++nt) {
                const float* c = C[mt][nt];
                const int r0 = rowBase + mt * 16 + fg;
                const int col = colBase + nt * 8 + ft2;
                *(float2*)&sC[r0 * SC_STRIDE + col]       = make_float2(c[0], c[1]);
                *(float2*)&sC[(r0 + 8) * SC_STRIDE + col] = make_float2(c[2], c[3]);
            }
        __syncthreads();
        if (rowOK) {
            const float4* rowp = (const float4*)(sC + tid * SC_STRIDE);
            float4* drow = (float4*)(dstF + (size_t)(nBase + tid) * CCH);
#pragma unroll
            for (int c4 = 0; c4 < 16; ++c4) drow[c4] = rowp[c4];
        }
    }
}

// out = BN3(out) + BN1(y2h)
__global__ __launch_bounds__(256)
void final_k(float* __restrict__ out, const __half* __restrict__ y2h,
             const float* __restrict__ g1_, const float* __restrict__ b1_,
             const float* __restrict__ g3_, const float* __restrict__ b3_,
             float invN, int total4)
{
    __shared__ float c1[64], s1[64], c3[64], s3[64];
    const int tid = threadIdx.x;
    if (tid < 64) {
        const float m1 = g_sums[1][tid] * invN;
        const float v1 = g_sumsq[1][tid] * invN - m1 * m1;
        const float a1 = g1_[tid] * rsqrtf(v1 + EPS_BN);
        c1[tid] = a1; s1[tid] = b1_[tid] - m1 * a1;
        const float m3 = g_sums[3][tid] * invN;
        const float v3 = g_sumsq[3][tid] * invN - m3 * m3;
        const float a3 = g3_[tid] * rsqrtf(v3 + EPS_BN);
        c3[tid] = a3; s3[tid] = b3_[tid] - m3 * a3;
    }
    __syncthreads();
    const int i = blockIdx.x * 256 + tid;
    if (i >= total4) return;
    float4 a = ((float4*)out)[i];
    const uint2 hb = ((const uint2*)y2h)[i];
    const __half2 p0 = *(const __half2*)&hb.x;
    const __half2 p1 = *(const __half2*)&hb.y;
    const float bx = __low2float(p0), by = __high2float(p0);
    const float bz = __low2float(p1), bw = __high2float(p1);
    const int c = (i * 4) & 63;
    a.x = fmaf(a.x, c3[c + 0], s3[c + 0]) + fmaf(bx, c1[c + 0], s1[c + 0]);
    a.y = fmaf(a.y, c3[c + 1], s3[c + 1]) + fmaf(by, c1[c + 1], s1[c + 1]);
    a.z = fmaf(a.z, c3[c + 2], s3[c + 2]) + fmaf(bz, c1[c + 2], s1[c + 2]);
    a.w = fmaf(a.w, c3[c + 3], s3[c + 3]) + fmaf(bw, c1[c + 3], s1[c + 3]);
    ((float4*)out)[i] = a;
}

// ---------------- launcher ----------------
extern "C" void kernel_launch(void* const* d_in, const int* in_sizes, int n_in,
                              void* d_out, int out_size)
{
    const float* features = (const float*)d_in[0];
    const float* w1   = (const float*)d_in[1];
    const float* w1_2 = (const float*)d_in[2];
    const float* w2   = (const float*)d_in[3];
    const float* w3   = (const float*)d_in[4];
    const float* g0   = (const float*)d_in[5];
    const float* b0   = (const float*)d_in[6];
    const float* g0_2 = (const float*)d_in[7];
    const float* b0_2 = (const float*)d_in[8];
    const float* g1   = (const float*)d_in[9];
    const float* b1   = (const float*)d_in[10];
    const float* g2   = (const float*)d_in[11];
    const float* b2   = (const float*)d_in[12];
    const int*   nbr13 = (const int*)d_in[13];
    const int*   nbr31 = (const int*)d_in[14];

    const int nTotal = in_sizes[0] / CCH;
    const float invN = 1.0f / (float)nTotal;
    const int grid   = (nTotal + TN - 1) / TN;
    const int gridS  = (nTotal + 255) / 256;

    cudaFuncSetAttribute(conv_mma_k<false>,
                         cudaFuncAttributeMaxDynamicSharedMemorySize, DSM_BYTES);
    cudaFuncSetAttribute(conv_mma_k<true>,
                         cudaFuncAttributeMaxDynamicSharedMemorySize, DSM_BYTES);

    __half *fS = nullptr, *aSa = nullptr, *aSb = nullptr, *y2h = nullptr;
    cudaGetSymbolAddress((void**)&fS,  g_fS);
    cudaGetSymbolAddress((void**)&aSa, g_aSa);
    cudaGetSymbolAddress((void**)&aSb, g_aSb);
    cudaGetSymbolAddress((void**)&y2h, g_y2h);
    float* out = (float*)d_out;

    pre_k<<<gridS + 2 * KTAPS + 1, 256>>>(features, w1, w2, nTotal, gridS);

    // phase A: conv0 (nbr13, w1 -> aSa, stats0) || conv2 (nbr31, w2 -> aSb, stats2)
    {
        dim3 g2d(grid, 2);
        conv_mma_k<false><<<g2d, NTHR, DSM_BYTES>>>(
            fS, fS, nbr13, nbr31, 0, 2,
            nullptr, nullptr, aSa, aSb, 1, 1, nTotal, 0, 2);
    }

    prep_fold2_k<<<2 * KTAPS, 256>>>(w1_2, w3, g0, b0, g1, b1, invN);

    // phase B: conv1 (aSa, nbr31 -> y2h fp16, stats1) || conv3 (aSb, nbr13 -> out fp32, stats3)
    {
        dim3 g2d(grid, 2);
        conv_mma_k<true><<<g2d, NTHR, DSM_BYTES>>>(
            aSa, aSb, nbr31, nbr13, 1, 3,
            nullptr, out, y2h, nullptr, 2, 0, nTotal, 1, 3);
    }

    const int total4 = nTotal * CCH / 4;
    final_k<<<(total4 + 255) / 256, 256>>>(out, y2h, g0_2, b0_2, g2, b2, invN, total4);
}